// round 6
// baseline (speedup 1.0000x reference)
#include <cuda_runtime.h>
#include <stdint.h>

// Coarse key space: 128^3 = 2^21, key = (bx<<14)|(by<<7)|bz.
// Numeric key order == lexicographic row order of jnp.unique. No sort needed.
#define NKEYS   (1 << 21)
#define TILE    1024
#define NTILES  (NKEYS / TILE)   // 2048
#define MAXN    600000

__device__ unsigned int g_flags[NKEYS];     // presence -> overwritten in place with exclusive prefix (rank)
__device__ unsigned int g_bsum[NTILES];     // per-tile sums -> scanned in place
__device__ int          g_winner[MAXN * 8]; // last-writer point index per (rank, offset) slot, -1 = empty

__device__ __forceinline__ unsigned pack_key(int cx, int cy, int cz) {
    return ((unsigned)(cx >> 1) << 14) | ((unsigned)(cy >> 1) << 7) | (unsigned)(cz >> 1);
}

// ---------------------------------------------------------------------------
// Init scratch: presence flags = 0, winner slots = -1.
__global__ void k_init(int n8) {
    int i = blockIdx.x * blockDim.x + threadIdx.x;
    if (i < NKEYS) g_flags[i] = 0u;
    if (i < n8)    g_winner[i] = -1;
}

// Fill the unique_coords output region with -1.0f (the jnp.unique fill value,
// compared by the harness in FLOAT space — this was the NaN bug).
__global__ void k_fill_ucoords(float* __restrict__ uc, int n3) {
    int i = blockIdx.x * blockDim.x + threadIdx.x;
    if (i < n3) uc[i] = -1.0f;
}

__global__ void k_mark(const int* __restrict__ coords, int n) {
    int i = blockIdx.x * blockDim.x + threadIdx.x;
    if (i >= n) return;
    int cx = coords[3 * i], cy = coords[3 * i + 1], cz = coords[3 * i + 2];
    g_flags[pack_key(cx, cy, cz)] = 1u;
}

// Per-tile reduction: 256 threads x uint4 each over one 1024-flag tile.
__global__ void k_reduce() {
    int b = blockIdx.x, t = threadIdx.x;
    const uint4* p = (const uint4*)(g_flags + (size_t)b * TILE);
    uint4 v = p[t];
    unsigned s = v.x + v.y + v.z + v.w;
    #pragma unroll
    for (int o = 16; o > 0; o >>= 1) s += __shfl_down_sync(0xFFFFFFFFu, s, o);
    __shared__ unsigned ws[8];
    if ((t & 31) == 0) ws[t >> 5] = s;
    __syncthreads();
    if (t == 0) {
        unsigned tot = 0;
        #pragma unroll
        for (int w = 0; w < 8; w++) tot += ws[w];
        g_bsum[b] = tot;
    }
}

// Single block: exclusive scan of the 2048 tile sums in place.
__global__ void k_scan_sums() {
    int t = threadIdx.x;
    unsigned v[8], s = 0;
    #pragma unroll
    for (int j = 0; j < 8; j++) { v[j] = g_bsum[t * 8 + j]; s += v[j]; }
    unsigned lane = t & 31, w = t >> 5;
    unsigned incl = s;
    #pragma unroll
    for (int o = 1; o < 32; o <<= 1) {
        unsigned x = __shfl_up_sync(0xFFFFFFFFu, incl, o);
        if (lane >= o) incl += x;
    }
    __shared__ unsigned wsum[8], woff[8];
    if (lane == 31) wsum[w] = incl;
    __syncthreads();
    if (t == 0) { unsigned a = 0; for (int i = 0; i < 8; i++) { woff[i] = a; a += wsum[i]; } }
    __syncthreads();
    unsigned run = woff[w] + (incl - s);   // exclusive base for this thread
    #pragma unroll
    for (int j = 0; j < 8; j++) { g_bsum[t * 8 + j] = run; run += v[j]; }
}

// Per-tile exclusive scan; flags <- global rank in place; emit sorted unique
// coarse coords AS FLOATS into the output (rows beyond U keep the -1.0f fill).
__global__ void k_scan_write(float* __restrict__ ucoords) {
    int b = blockIdx.x, t = threadIdx.x;
    uint4* p = (uint4*)(g_flags + (size_t)b * TILE);
    uint4 v = p[t];
    unsigned vals[4] = { v.x, v.y, v.z, v.w };
    unsigned s = vals[0] + vals[1] + vals[2] + vals[3];
    unsigned lane = t & 31, w = t >> 5;
    unsigned incl = s;
    #pragma unroll
    for (int o = 1; o < 32; o <<= 1) {
        unsigned x = __shfl_up_sync(0xFFFFFFFFu, incl, o);
        if (lane >= o) incl += x;
    }
    __shared__ unsigned wsum[8], woff[8];
    if (lane == 31) wsum[w] = incl;
    __syncthreads();
    if (t == 0) { unsigned a = 0; for (int i = 0; i < 8; i++) { woff[i] = a; a += wsum[i]; } }
    __syncthreads();
    unsigned run = g_bsum[b] + woff[w] + (incl - s);
    unsigned keybase = (unsigned)b * TILE + (unsigned)t * 4;
    unsigned pf[4];
    #pragma unroll
    for (int j = 0; j < 4; j++) {
        pf[j] = run;
        if (vals[j]) {
            unsigned key = keybase + j;
            unsigned r = run;
            ucoords[3 * r]     = (float)(key >> 14);
            ucoords[3 * r + 1] = (float)((key >> 7) & 127u);
            ucoords[3 * r + 2] = (float)(key & 127u);
        }
        run += vals[j];
    }
    p[t] = make_uint4(pf[0], pf[1], pf[2], pf[3]);
}

// Last-index-wins arbitration per (rank, offset) slot — matches sequential
// scatter semantics of the reference deterministically.
__global__ void k_winner(const int* __restrict__ coords, int n) {
    int i = blockIdx.x * blockDim.x + threadIdx.x;
    if (i >= n) return;
    int cx = coords[3 * i], cy = coords[3 * i + 1], cz = coords[3 * i + 2];
    unsigned rank = g_flags[pack_key(cx, cy, cz)];
    int off = ((cx & 1) << 2) | ((cy & 1) << 1) | (cz & 1);
    atomicMax(&g_winner[rank * 8 + off], i);
}

// Row writer: one warp per output row (128 floats = 32 float4). Each lane owns
// float4 #lane: slot = lane>>2, quarter = lane&3. Gathers the winning point's
// feats (or zeros) and streams one contiguous 512B store per row. Every agg
// byte is written exactly once — no memset, no double-write. Rows with no
// winners (rank >= U) come out all-zero, matching the reference fill rows.
__global__ void k_rows(const float* __restrict__ feats,
                       float4* __restrict__ agg4, int n) {
    int warp = (blockIdx.x * blockDim.x + threadIdx.x) >> 5;
    int lane = threadIdx.x & 31;
    if (warp >= n) return;
    int slot = lane >> 2, q = lane & 3;
    int w = g_winner[warp * 8 + slot];
    float4 f = make_float4(0.f, 0.f, 0.f, 0.f);
    if (w >= 0) f = ((const float4*)feats)[(size_t)w * 4 + q];
    agg4[(size_t)warp * 32 + lane] = f;
}

// Scalar fallback if the agg region isn't 16B-aligned (defensive; not expected).
__global__ void k_rows_scalar(const float* __restrict__ feats,
                              float* __restrict__ agg, int n) {
    long long g = (long long)blockIdx.x * blockDim.x + threadIdx.x;
    long long total = (long long)n * 128;
    if (g >= total) return;
    int r = (int)(g >> 7), c = (int)(g & 127);
    int w = g_winner[r * 8 + (c >> 4)];
    agg[g] = (w >= 0) ? feats[(size_t)w * 16 + (c & 15)] : 0.f;
}

// ---------------------------------------------------------------------------
extern "C" void kernel_launch(void* const* d_in, const int* in_sizes, int n_in,
                              void* d_out, int out_size) {
    // metadata order: feats (N*16 f32), coords (N*3 i32). Defensive swap check.
    int fi = 0, ci = 1;
    if (in_sizes[0] < in_sizes[1]) { fi = 1; ci = 0; }
    const float* feats  = (const float*)d_in[fi];
    const int*   coords = (const int*)d_in[ci];
    int n = in_sizes[ci] / 3;

    float* ucoords = (float*)d_out;                     // [n,3]  unique coarse coords AS FLOAT
    float* agg     = (float*)d_out + (size_t)n * 3;     // [n,128] aggregated features

    int n8 = n * 8;
    int initN = (NKEYS > n8) ? NKEYS : n8;
    k_init        <<<(initN + 255) / 256, 256>>>(n8);
    k_fill_ucoords<<<(n * 3 + 255) / 256, 256>>>(ucoords, n * 3);
    k_mark        <<<(n + 255) / 256, 256>>>(coords, n);
    k_reduce      <<<NTILES, 256>>>();
    k_scan_sums   <<<1, 256>>>();
    k_scan_write  <<<NTILES, 256>>>(ucoords);
    k_winner      <<<(n + 255) / 256, 256>>>(coords, n);

    if ((((uintptr_t)agg) & 15) == 0) {
        // 1 warp per row, 8 rows per 256-thread block
        k_rows<<<(n + 7) / 8, 256>>>(feats, (float4*)agg, n);
    } else {
        long long total = (long long)n * 128;
        k_rows_scalar<<<(unsigned)((total + 255) / 256), 256>>>(feats, agg, n);
    }
}

// round 8
// speedup vs baseline: 1.1658x; 1.1658x over previous
#include <cuda_runtime.h>
#include <stdint.h>

// Coarse key space: 128^3 = 2^21, key = (bx<<14)|(by<<7)|bz.
// Numeric key order == lexicographic row order of jnp.unique. No sort needed.
#define NKEYS   (1 << 21)
#define NWORDS  (NKEYS / 64)     // 32768 u64 presence words = 256 KB (L2-resident)
#define NBLK    128              // scan blocks: 128 x 256 threads x 1 word
#define MAXN    600000

__device__ unsigned long long g_bits[NWORDS];  // presence bitmap
__device__ unsigned           g_rank[NKEYS];   // rank per key; written/read ONLY at present keys (no init)
__device__ unsigned           g_bsum[NBLK];    // per-scan-block popcount sums
__device__ int                g_winner[MAXN * 8]; // last-writer point idx per (rank, offset) slot

__device__ __forceinline__ unsigned pack_key(int cx, int cy, int cz) {
    return ((unsigned)(cx >> 1) << 14) | ((unsigned)(cy >> 1) << 7) | (unsigned)(cz >> 1);
}

// ---------------------------------------------------------------------------
// Fused init: clear bitmap (256 KB), winner = -1 (int4-vectorized, 16 MB),
// ucoords fill = -1.0f (6 MB). One launch.
__global__ void k_init(float* __restrict__ uc, int n) {
    int i = blockIdx.x * blockDim.x + threadIdx.x;
    if (i < NWORDS) g_bits[i] = 0ull;
    if (i < n * 2)  ((int4*)g_winner)[i] = make_int4(-1, -1, -1, -1);  // n*8 ints = n*2 int4
    if (i < n * 3)  uc[i] = -1.0f;
}

// Set presence bits. 500k atomicOr into a 256 KB L2-resident array.
__global__ void k_mark(const int* __restrict__ coords, int n) {
    int i = blockIdx.x * blockDim.x + threadIdx.x;
    if (i >= n) return;
    int cx = coords[3 * i], cy = coords[3 * i + 1], cz = coords[3 * i + 2];
    unsigned key = pack_key(cx, cy, cz);
    atomicOr(&g_bits[key >> 6], 1ull << (key & 63));
}

// Per-block popcount sums over the bitmap (128 blocks x 256 words).
__global__ void k_scan1() {
    int b = blockIdx.x, t = threadIdx.x;
    unsigned c = (unsigned)__popcll(g_bits[b * 256 + t]);
    #pragma unroll
    for (int o = 16; o > 0; o >>= 1) c += __shfl_down_sync(0xFFFFFFFFu, c, o);
    __shared__ unsigned ws[8];
    if ((t & 31) == 0) ws[t >> 5] = c;
    __syncthreads();
    if (t == 0) {
        unsigned tot = 0;
        #pragma unroll
        for (int w = 0; w < 8; w++) tot += ws[w];
        g_bsum[b] = tot;
    }
}

// Scan + emit: each block computes its global base from g_bsum (NBLK=128 is
// tiny), block-scans per-word popcounts, then walks set bits in ascending key
// order, writing rank into g_rank[key] and the sorted unique coarse coords AS
// FLOATS (rows beyond U keep the -1.0f fill).
__global__ void k_scan_write(float* __restrict__ ucoords) {
    int b = blockIdx.x, t = threadIdx.x;

    // Block base = sum of previous blocks' counts (reduce 128 masked values).
    __shared__ unsigned red[256];
    red[t] = (t < b) ? g_bsum[t] : 0u;   // t in [0,256), b <= 128
    __syncthreads();
    #pragma unroll
    for (int s = 128; s > 0; s >>= 1) {
        if (t < s) red[t] += red[t + s];
        __syncthreads();
    }
    unsigned blockBase = red[0];
    __syncthreads();

    unsigned long long word = g_bits[b * 256 + t];
    unsigned c = (unsigned)__popcll(word);
    unsigned lane = t & 31, w = t >> 5;
    unsigned incl = c;
    #pragma unroll
    for (int o = 1; o < 32; o <<= 1) {
        unsigned x = __shfl_up_sync(0xFFFFFFFFu, incl, o);
        if (lane >= o) incl += x;
    }
    __shared__ unsigned wsum[8], woff[8];
    if (lane == 31) wsum[w] = incl;
    __syncthreads();
    if (t == 0) { unsigned a = 0; for (int i = 0; i < 8; i++) { woff[i] = a; a += wsum[i]; } }
    __syncthreads();

    unsigned r = blockBase + woff[w] + (incl - c);   // exclusive prefix for this word
    unsigned keybase = ((unsigned)b * 256 + (unsigned)t) * 64;
    unsigned long long m = word;
    while (m) {
        int bit = __ffsll((long long)m) - 1;
        unsigned key = keybase + (unsigned)bit;
        g_rank[key] = r;
        ucoords[3 * r]     = (float)(key >> 14);
        ucoords[3 * r + 1] = (float)((key >> 7) & 127u);
        ucoords[3 * r + 2] = (float)(key & 127u);
        r++;
        m &= m - 1;
    }
}

// Last-index-wins arbitration per (rank, offset) slot — deterministic match of
// the reference's sequential scatter semantics.
__global__ void k_winner(const int* __restrict__ coords, int n) {
    int i = blockIdx.x * blockDim.x + threadIdx.x;
    if (i >= n) return;
    int cx = coords[3 * i], cy = coords[3 * i + 1], cz = coords[3 * i + 2];
    unsigned rank = g_rank[pack_key(cx, cy, cz)];
    int off = ((cx & 1) << 2) | ((cy & 1) << 1) | (cz & 1);
    atomicMax(&g_winner[rank * 8 + off], i);
}

// Row writer: one warp per output row (128 floats = 32 float4). Lane L owns
// float4 #L: slot = L>>2, quarter = L&3; lanes of a slot read a contiguous
// 64B feats segment. Every agg byte is written exactly once, streamed with
// .cs (never re-read — keep L2 for the bitmap/rank/winner structures).
__global__ void k_rows(const float* __restrict__ feats,
                       float4* __restrict__ agg4, int n) {
    int warp = (blockIdx.x * blockDim.x + threadIdx.x) >> 5;
    int lane = threadIdx.x & 31;
    if (warp >= n) return;
    int slot = lane >> 2, q = lane & 3;
    int w = g_winner[warp * 8 + slot];
    float4 f = make_float4(0.f, 0.f, 0.f, 0.f);
    if (w >= 0) f = __ldg(&((const float4*)feats)[(size_t)w * 4 + q]);
    __stcs(&agg4[(size_t)warp * 32 + lane], f);
}

// Scalar fallback if agg isn't 16B-aligned (defensive; not expected).
__global__ void k_rows_scalar(const float* __restrict__ feats,
                              float* __restrict__ agg, int n) {
    long long g = (long long)blockIdx.x * blockDim.x + threadIdx.x;
    long long total = (long long)n * 128;
    if (g >= total) return;
    int r = (int)(g >> 7), c = (int)(g & 127);
    int w = g_winner[r * 8 + (c >> 4)];
    agg[g] = (w >= 0) ? feats[(size_t)w * 16 + (c & 15)] : 0.f;
}

// ---------------------------------------------------------------------------
extern "C" void kernel_launch(void* const* d_in, const int* in_sizes, int n_in,
                              void* d_out, int out_size) {
    // metadata order: feats (N*16 f32), coords (N*3 i32). Defensive swap check.
    int fi = 0, ci = 1;
    if (in_sizes[0] < in_sizes[1]) { fi = 1; ci = 0; }
    const float* feats  = (const float*)d_in[fi];
    const int*   coords = (const int*)d_in[ci];
    int n = in_sizes[ci] / 3;

    float* ucoords = (float*)d_out;                     // [n,3]  unique coarse coords AS FLOAT
    float* agg     = (float*)d_out + (size_t)n * 3;     // [n,128] aggregated features

    int initN = n * 3;                                   // covers n*2 int4s, n*3 floats, NWORDS
    if (n * 2 > initN) initN = n * 2;
    if (NWORDS > initN) initN = NWORDS;

    k_init      <<<(initN + 255) / 256, 256>>>(ucoords, n);
    k_mark      <<<(n + 255) / 256, 256>>>(coords, n);
    k_scan1     <<<NBLK, 256>>>();
    k_scan_write<<<NBLK, 256>>>(ucoords);
    k_winner    <<<(n + 255) / 256, 256>>>(coords, n);

    if ((((uintptr_t)agg) & 15) == 0) {
        k_rows<<<(n + 7) / 8, 256>>>(feats, (float4*)agg, n);   // 1 warp/row, 8 rows/block
    } else {
        long long total = (long long)n * 128;
        k_rows_scalar<<<(unsigned)((total + 255) / 256), 256>>>(feats, agg, n);
    }
}

// round 9
// speedup vs baseline: 1.1914x; 1.0219x over previous
#include <cuda_runtime.h>
#include <stdint.h>

// Coarse key space: 128^3 = 2^21, key = (bx<<14)|(by<<7)|bz.
// Numeric key order == lexicographic row order of jnp.unique. No sort needed.
#define NKEYS   (1 << 21)
#define NWORDS  (NKEYS / 64)     // 32768 u64 presence words = 256 KB (L2-resident)
#define NBLK    128              // scan blocks: 128 x 256 threads x 1 word
#define MAXN    600000

__device__ unsigned long long g_bits[NWORDS];  // presence bitmap
__device__ unsigned           g_wpfx[NWORDS];  // exclusive prefix (rank base) per word
__device__ unsigned           g_rank[NKEYS];   // rank per key; touched ONLY at present keys (no init)
__device__ unsigned           g_bsum[NBLK];    // per-scan-block popcount sums
__device__ int                g_winner[MAXN * 8]; // last-writer point idx per (rank, offset) slot

__device__ __forceinline__ unsigned pack_key(int cx, int cy, int cz) {
    return ((unsigned)(cx >> 1) << 14) | ((unsigned)(cy >> 1) << 7) | (unsigned)(cz >> 1);
}

// ---------------------------------------------------------------------------
// Fused init: clear bitmap (256 KB), winner = -1 (int4-vectorized, 16 MB),
// ucoords fill = -1.0f (6 MB). One launch.
__global__ void k_init(float* __restrict__ uc, int n) {
    int i = blockIdx.x * blockDim.x + threadIdx.x;
    if (i < NWORDS) g_bits[i] = 0ull;
    if (i < n * 2)  ((int4*)g_winner)[i] = make_int4(-1, -1, -1, -1);  // n*8 ints = n*2 int4
    if (i < n * 3)  uc[i] = -1.0f;
}

// Set presence bits. 500k atomicOr into a 256 KB L2-resident array.
__global__ void k_mark(const int* __restrict__ coords, int n) {
    int i = blockIdx.x * blockDim.x + threadIdx.x;
    if (i >= n) return;
    int cx = coords[3 * i], cy = coords[3 * i + 1], cz = coords[3 * i + 2];
    unsigned key = pack_key(cx, cy, cz);
    atomicOr(&g_bits[key >> 6], 1ull << (key & 63));
}

// Per-block popcount sums over the bitmap (128 blocks x 256 words).
__global__ void k_scan1() {
    int b = blockIdx.x, t = threadIdx.x;
    unsigned c = (unsigned)__popcll(g_bits[b * 256 + t]);
    #pragma unroll
    for (int o = 16; o > 0; o >>= 1) c += __shfl_down_sync(0xFFFFFFFFu, c, o);
    __shared__ unsigned ws[8];
    if ((t & 31) == 0) ws[t >> 5] = c;
    __syncthreads();
    if (t == 0) {
        unsigned tot = 0;
        #pragma unroll
        for (int w = 0; w < 8; w++) tot += ws[w];
        g_bsum[b] = tot;
    }
}

// Per-word exclusive prefix (rank base): block base from g_bsum + intra-block
// scan of word popcounts. NO bit walk — just one store per word.
__global__ void k_wpfx() {
    int b = blockIdx.x, t = threadIdx.x;

    __shared__ unsigned red[256];
    red[t] = (t < b) ? g_bsum[t] : 0u;   // b <= 127 < 256
    __syncthreads();
    #pragma unroll
    for (int s = 128; s > 0; s >>= 1) {
        if (t < s) red[t] += red[t + s];
        __syncthreads();
    }
    unsigned blockBase = red[0];
    __syncthreads();

    unsigned c = (unsigned)__popcll(g_bits[b * 256 + t]);
    unsigned lane = t & 31, w = t >> 5;
    unsigned incl = c;
    #pragma unroll
    for (int o = 1; o < 32; o <<= 1) {
        unsigned x = __shfl_up_sync(0xFFFFFFFFu, incl, o);
        if (lane >= o) incl += x;
    }
    __shared__ unsigned wsum[8], woff[8];
    if (lane == 31) wsum[w] = incl;
    __syncthreads();
    if (t == 0) { unsigned a = 0; for (int i = 0; i < 8; i++) { woff[i] = a; a += wsum[i]; } }
    __syncthreads();

    g_wpfx[b * 256 + t] = blockBase + woff[w] + (incl - c);
}

// One thread per KEY (2M threads): fully parallel rank + coord emit.
// rank = wpfx[word] + popc(lower bits). Rank is monotone in key, so
// consecutive present keys write consecutive ucoords rows (coalesced-ish).
// Word/wpfx loads are broadcast within each half-warp.
__global__ void k_emit(float* __restrict__ ucoords) {
    unsigned k = blockIdx.x * blockDim.x + threadIdx.x;
    if (k >= NKEYS) return;
    unsigned long long word = g_bits[k >> 6];
    unsigned bit = k & 63u;
    if (!((word >> bit) & 1ull)) return;
    unsigned r = g_wpfx[k >> 6] +
                 (unsigned)__popcll(word & ((1ull << bit) - 1ull));
    g_rank[k] = r;
    ucoords[3 * r]     = (float)(k >> 14);
    ucoords[3 * r + 1] = (float)((k >> 7) & 127u);
    ucoords[3 * r + 2] = (float)(k & 127u);
}

// Last-index-wins arbitration per (rank, offset) slot — deterministic match of
// the reference's sequential scatter semantics.
__global__ void k_winner(const int* __restrict__ coords, int n) {
    int i = blockIdx.x * blockDim.x + threadIdx.x;
    if (i >= n) return;
    int cx = coords[3 * i], cy = coords[3 * i + 1], cz = coords[3 * i + 2];
    unsigned rank = g_rank[pack_key(cx, cy, cz)];
    int off = ((cx & 1) << 2) | ((cy & 1) << 1) | (cz & 1);
    atomicMax(&g_winner[rank * 8 + off], i);
}

// Row writer: one warp per output row (128 floats = 32 float4). Lane L owns
// float4 #L: slot = L>>2, quarter = L&3; lanes of a slot read a contiguous
// 64B feats segment. Every agg byte is written exactly once, streamed with
// .cs (never re-read — keep L2 for the bitmap/rank/winner structures).
__global__ void k_rows(const float* __restrict__ feats,
                       float4* __restrict__ agg4, int n) {
    int warp = (blockIdx.x * blockDim.x + threadIdx.x) >> 5;
    int lane = threadIdx.x & 31;
    if (warp >= n) return;
    int slot = lane >> 2, q = lane & 3;
    int w = g_winner[warp * 8 + slot];
    float4 f = make_float4(0.f, 0.f, 0.f, 0.f);
    if (w >= 0) f = __ldg(&((const float4*)feats)[(size_t)w * 4 + q]);
    __stcs(&agg4[(size_t)warp * 32 + lane], f);
}

// Scalar fallback if agg isn't 16B-aligned (defensive; not expected).
__global__ void k_rows_scalar(const float* __restrict__ feats,
                              float* __restrict__ agg, int n) {
    long long g = (long long)blockIdx.x * blockDim.x + threadIdx.x;
    long long total = (long long)n * 128;
    if (g >= total) return;
    int r = (int)(g >> 7), c = (int)(g & 127);
    int w = g_winner[r * 8 + (c >> 4)];
    agg[g] = (w >= 0) ? feats[(size_t)w * 16 + (c & 15)] : 0.f;
}

// ---------------------------------------------------------------------------
extern "C" void kernel_launch(void* const* d_in, const int* in_sizes, int n_in,
                              void* d_out, int out_size) {
    // metadata order: feats (N*16 f32), coords (N*3 i32). Defensive swap check.
    int fi = 0, ci = 1;
    if (in_sizes[0] < in_sizes[1]) { fi = 1; ci = 0; }
    const float* feats  = (const float*)d_in[fi];
    const int*   coords = (const int*)d_in[ci];
    int n = in_sizes[ci] / 3;

    float* ucoords = (float*)d_out;                     // [n,3]  unique coarse coords AS FLOAT
    float* agg     = (float*)d_out + (size_t)n * 3;     // [n,128] aggregated features

    int initN = n * 3;                                   // covers n*2 int4s, n*3 floats, NWORDS
    if (n * 2 > initN) initN = n * 2;
    if (NWORDS > initN) initN = NWORDS;

    k_init  <<<(initN + 255) / 256, 256>>>(ucoords, n);
    k_mark  <<<(n + 255) / 256, 256>>>(coords, n);
    k_scan1 <<<NBLK, 256>>>();
    k_wpfx  <<<NBLK, 256>>>();
    k_emit  <<<NKEYS / 256, 256>>>(ucoords);
    k_winner<<<(n + 255) / 256, 256>>>(coords, n);

    if ((((uintptr_t)agg) & 15) == 0) {
        k_rows<<<(n + 7) / 8, 256>>>(feats, (float4*)agg, n);   // 1 warp/row, 8 rows/block
    } else {
        long long total = (long long)n * 128;
        k_rows_scalar<<<(unsigned)((total + 255) / 256), 256>>>(feats, agg, n);
    }
}